// round 8
// baseline (speedup 1.0000x reference)
#include <cuda_runtime.h>
#include <cuda_bf16.h>
#include <cstdint>

// Problem constants
#define Bq   1024
#define Nn   128
#define Dd   256
#define Hh   8
#define NB   2
#define NEGV (-1e9f)
#define CLIPV 10.0f
#define INV_SQRT_DH 0.17677669529663687f  // 1/sqrt(32)
#define INV_SQRT_D  0.0625f               // 1/sqrt(256)

#define ROWS_TOTAL (Bq * Nn)              // 131072

// ---------------- scratch (device globals; no cudaMalloc allowed) ----------
__device__ float g_K   [Bq * Nn * Dd];   // [b][n][d]  (E@Wk)
__device__ float g_V   [Bq * Nn * Dd];   // [b][n][d]  (E@Wv)
__device__ float g_LK2 [Bq * Nn * Dd];   // [b][n][d]  (E@(Wlk@Wo^T))
__device__ float g_P   [Bq * Nn * Dd];   // [b][n][d]  (E@Ws_bot)
__device__ float g_q0  [Bq * Dd];        // step-0 query (pre-MLP)
__device__ float g_Woc [Dd * Dd];        // Wo@Wc
__device__ float g_Wlk2[Dd * Dd];        // Wlk@Wo^T
__device__ float g_WoT [Dd * Dd];        // Wo^T
__device__ float g_pc  [Dd];             // W_placeholder @ Ws
__device__ int   g_mlp;                  // 1 if (W2,b2) nonzero -> general path

// bf16 3-way exact splits (x = s0+s1+s2 exactly for fp32 inputs)
__device__ __nv_bfloat16 g_Es[3][ROWS_TOTAL * Dd];     // E splits
__device__ __nv_bfloat16 g_Wt[3][4][Dd * Dd];          // W^T splits [s][w][n][k]

// ================= helpers ==================================================
__device__ __forceinline__ uint32_t smem_u32(const void* p) {
    uint32_t a;
    asm("{ .reg .u64 t; cvta.to.shared.u64 t, %1; cvt.u32.u64 %0, t; }"
        : "=r"(a) : "l"(p));
    return a;
}
#define SW128(x) ((x) ^ (((x) >> 3) & 0x70))

__device__ __forceinline__ void ldsm_x4(uint32_t* r, uint32_t addr) {
    asm volatile("ldmatrix.sync.aligned.m8n8.x4.shared.b16 {%0,%1,%2,%3}, [%4];"
        : "=r"(r[0]), "=r"(r[1]), "=r"(r[2]), "=r"(r[3]) : "r"(addr));
}
__device__ __forceinline__ void ldsm_x2(uint32_t* r, uint32_t addr) {
    asm volatile("ldmatrix.sync.aligned.m8n8.x2.shared.b16 {%0,%1}, [%2];"
        : "=r"(r[0]), "=r"(r[1]) : "r"(addr));
}
__device__ __forceinline__ void mma_bf16(float* c, const uint32_t* a, const uint32_t* b) {
    asm volatile("mma.sync.aligned.m16n8k16.row.col.f32.bf16.bf16.f32 "
        "{%0,%1,%2,%3}, {%4,%5,%6,%7}, {%8,%9}, {%0,%1,%2,%3};"
        : "+f"(c[0]), "+f"(c[1]), "+f"(c[2]), "+f"(c[3])
        : "r"(a[0]), "r"(a[1]), "r"(a[2]), "r"(a[3]), "r"(b[0]), "r"(b[1]));
}

// ---------------- k0: transpose Wo, detect MLP-nonzero ---------------------
__global__ void k0_prep(const float* __restrict__ Wo,
                        const float* __restrict__ W2,
                        const float* __restrict__ b2)
{
    if (blockIdx.x == 0) {
        for (int i = threadIdx.x; i < Dd * Dd; i += blockDim.x) {
            int k = i >> 8, d = i & 255;
            g_WoT[d * Dd + k] = Wo[k * Dd + d];
        }
    } else {
        __shared__ int any;
        if (threadIdx.x == 0) any = 0;
        __syncthreads();
        int loc = 0;
        for (int i = threadIdx.x; i < Dd * Dd; i += blockDim.x)
            loc |= (W2[i] != 0.0f);
        if (threadIdx.x < Dd) loc |= (b2[threadIdx.x] != 0.0f);
        if (loc) atomicOr(&any, 1);
        __syncthreads();
        if (threadIdx.x == 0) g_mlp = any;
    }
}

// ---------------- k1: Woc = Wo@Wc ; Wlk2 = Wlk@Wo^T ; pc = placeholder@Ws --
__global__ void k1_weights(const float* __restrict__ Wo,
                           const float* __restrict__ Wc,
                           const float* __restrict__ Wlk,
                           const float* __restrict__ Ws,
                           const float* __restrict__ Wph)
{
    int bid = blockIdx.x;
    int d = threadIdx.x;
    if (bid < 256) {
        float acc = 0.f;
        #pragma unroll 8
        for (int j = 0; j < Dd; j++) acc += Wo[bid * Dd + j] * Wc[j * Dd + d];
        g_Woc[bid * Dd + d] = acc;
    } else if (bid < 512) {
        int m = bid - 256;
        float acc = 0.f;
        #pragma unroll 8
        for (int j = 0; j < Dd; j++) acc += Wlk[m * Dd + j] * g_WoT[j * Dd + d];
        g_Wlk2[m * Dd + d] = acc;
    } else {
        float acc = 0.f;
        #pragma unroll 8
        for (int k = 0; k < 2 * Dd; k++) acc += Wph[k] * Ws[k * Dd + d];
        g_pc[d] = acc;
    }
}

// ---------------- k2: q0 = mean_n(E) @ Wc + pc ------------------------------
__global__ void k2_q0(const float* __restrict__ E, const float* __restrict__ Wc)
{
    int b = blockIdx.x, d = threadIdx.x;
    __shared__ float g[Dd];
    float s = 0.f;
    const float* Eb = E + (size_t)b * Nn * Dd + d;
    #pragma unroll 8
    for (int n = 0; n < Nn; n++) s += Eb[n * Dd];
    g[d] = s * (1.0f / Nn);
    __syncthreads();
    float acc = g_pc[d];
    #pragma unroll 8
    for (int k = 0; k < Dd; k++) acc += g[k] * Wc[k * Dd + d];
    g_q0[b * Dd + d] = acc;
}

// ---------------- split kernels: exact fp32 -> 3x bf16 ----------------------
__global__ void k_splitE(const float* __restrict__ E)
{
    const size_t total = (size_t)ROWS_TOTAL * Dd;
    const size_t stride = (size_t)gridDim.x * blockDim.x;
    for (size_t i = (size_t)blockIdx.x * blockDim.x + threadIdx.x; i < total; i += stride) {
        float x = E[i];
        __nv_bfloat16 s0 = __float2bfloat16_rn(x);
        float r = x - __bfloat162float(s0);
        __nv_bfloat16 s1 = __float2bfloat16_rn(r);
        float r2 = r - __bfloat162float(s1);
        __nv_bfloat16 s2 = __float2bfloat16_rn(r2);
        g_Es[0][i] = s0; g_Es[1][i] = s1; g_Es[2][i] = s2;
    }
}

// transposed weight splits: g_Wt[s][w][n*256+k] = split_s(W_w[k][n])
__global__ void k_splitW(const float* __restrict__ Wk,
                         const float* __restrict__ Wv,
                         const float* __restrict__ Ws)
{
    const int w = blockIdx.x, n = blockIdx.y, k = threadIdx.x;
    const float* src;
    if      (w == 0) src = Wk;
    else if (w == 1) src = Wv;
    else if (w == 2) src = g_Wlk2;
    else             src = Ws + Dd * Dd;
    float x = src[k * Dd + n];
    __nv_bfloat16 s0 = __float2bfloat16_rn(x);
    float r = x - __bfloat162float(s0);
    __nv_bfloat16 s1 = __float2bfloat16_rn(r);
    float r2 = r - __bfloat162float(s1);
    __nv_bfloat16 s2 = __float2bfloat16_rn(r2);
    g_Wt[0][w][n * Dd + k] = s0;
    g_Wt[1][w][n * Dd + k] = s1;
    g_Wt[2][w][n * Dd + k] = s2;
}

// ---------------- k3t: mma.sync bf16-3split GEMM  out = E @ W --------------
// CTA tile 128m x 128n, 8 warps (each 32m x 64n), K chunked x64.
// 6 split passes (sa+sb<=2): exact to ~2^-24.
// smem: A 3x16KB + B 3x16KB = 96KB, SW128 swizzled, grid (1024, 2, 4).
static constexpr int K3_A_OFF = 0;
static constexpr int K3_B_OFF = 3 * 16384;
static constexpr int K3T_SMEM = 6 * 16384;   // 98304

__global__ void __launch_bounds__(256) k3t_mma()
{
    extern __shared__ char smem[];
    const uint32_t sbase = smem_u32(smem);
    const int tid = threadIdx.x;
    const int warp = tid >> 5, lane = tid & 31;
    const int rowbase = blockIdx.x * 128;
    const int nbase   = blockIdx.y * 128;
    const int w       = blockIdx.z;

    float* out;
    if      (w == 0) out = g_K;
    else if (w == 1) out = g_V;
    else if (w == 2) out = g_LK2;
    else             out = g_P;

    const int wm = warp & 3;      // 4 m-blocks of 32 rows
    const int wn = warp >> 2;     // 2 n-blocks of 64 cols

    float acc[2][8][4] = {};      // [mblk16][nblk8][frag]

    const __nv_bfloat16* Wt = g_Wt[0][0];  // silence unused warnings pattern

    for (int c = 0; c < 4; c++) {
        // ---- stage A splits: [3][128 rows][64 bf16] SW128 ------------------
        for (int i = tid; i < 3072; i += 256) {
            int s = i >> 10, rem = i & 1023;
            int row = rem >> 3, q = rem & 7;
            uint4 v = *(const uint4*)(&g_Es[s][(size_t)(rowbase + row) * Dd + c * 64 + q * 8]);
            *(uint4*)(smem + K3_A_OFF + s * 16384 + SW128(row * 128 + q * 16)) = v;
        }
        // ---- stage B splits: [3][128 n][64 k bf16] SW128 -------------------
        for (int i = tid; i < 3072; i += 256) {
            int s = i >> 10, rem = i & 1023;
            int n = rem >> 3, q = rem & 7;
            uint4 v = *(const uint4*)(&g_Wt[s][w][(size_t)(nbase + n) * Dd + c * 64 + q * 8]);
            *(uint4*)(smem + K3_B_OFF + s * 16384 + SW128(n * 128 + q * 16)) = v;
        }
        __syncthreads();

        #pragma unroll
        for (int ks = 0; ks < 4; ks++) {
            // A fragments for all 3 splits (ldmatrix.x4 per m16 block)
            uint32_t a_frag[3][2][4];
            #pragma unroll
            for (int s = 0; s < 3; s++)
                #pragma unroll
                for (int mb = 0; mb < 2; mb++) {
                    uint32_t off = (uint32_t)((wm * 32 + mb * 16 + (lane & 15)) * 128
                                              + ks * 32 + (lane >> 4) * 16);
                    ldsm_x4(a_frag[s][mb], sbase + K3_A_OFF + s * 16384 + SW128(off));
                }
            #pragma unroll
            for (int sb = 0; sb < 3; sb++) {
                uint32_t b_frag[8][2];
                #pragma unroll
                for (int nb = 0; nb < 8; nb++) {
                    uint32_t off = (uint32_t)((wn * 64 + nb * 8 + (lane & 7)) * 128
                                              + ks * 32 + ((lane >> 3) & 1) * 16);
                    ldsm_x2(b_frag[nb], sbase + K3_B_OFF + sb * 16384 + SW128(off));
                }
                #pragma unroll
                for (int sa = 0; sa <= 2 - sb; sa++)
                    #pragma unroll
                    for (int mb = 0; mb < 2; mb++)
                        #pragma unroll
                        for (int nb = 0; nb < 8; nb++)
                            mma_bf16(acc[mb][nb], a_frag[sa][mb], b_frag[nb]);
            }
        }
        __syncthreads();
    }
    (void)Wt;

    // ---- epilogue: fp32 stores -------------------------------------------
    const int r0 = rowbase + wm * 32 + (lane >> 2);
    const int c0 = nbase + wn * 64 + (lane & 3) * 2;
    #pragma unroll
    for (int mb = 0; mb < 2; mb++)
        #pragma unroll
        for (int nb = 0; nb < 8; nb++) {
            float2 lo = make_float2(acc[mb][nb][0], acc[mb][nb][1]);
            float2 hi = make_float2(acc[mb][nb][2], acc[mb][nb][3]);
            *(float2*)(out + (size_t)(r0 + mb * 16)     * Dd + c0 + nb * 8) = lo;
            *(float2*)(out + (size_t)(r0 + mb * 16 + 8) * Dd + c0 + nb * 8) = hi;
        }
}

// ---------------- k4: persistent decode, NB=2 batches per block -------------
struct K4Smem {
    float q[NB][Dd];
    float heads[NB][Dd];
    float cc[NB][Nn][9];
    float pp[NB][Hh][Nn + 4];
    float ls[NB][Nn];
    int   list[NB][Nn];
    float er[NB][Dd];
    float sum[NB][Hh];
    int   sel[NB];
    int   cnt;
};

__device__ __forceinline__ void k4_finalize_q(K4Smem& S, int tid, int mlp,
                                              const float* __restrict__ W1,
                                              const float* __restrict__ b1,
                                              const float* __restrict__ W2,
                                              const float* __restrict__ b2)
{
    if (mlp) {
        __syncthreads();
        float m1[NB];
        #pragma unroll
        for (int bb = 0; bb < NB; bb++) m1[bb] = b1[tid];
        #pragma unroll 8
        for (int k = 0; k < Dd; k++) {
            float wv = W1[k * Dd + tid];
            #pragma unroll
            for (int bb = 0; bb < NB; bb++) m1[bb] += S.q[bb][k] * wv;
        }
        #pragma unroll
        for (int bb = 0; bb < NB; bb++) S.er[bb][tid] = fmaxf(m1[bb], 0.0f);
        __syncthreads();
        float m2[NB];
        #pragma unroll
        for (int bb = 0; bb < NB; bb++) m2[bb] = b2[tid];
        #pragma unroll 8
        for (int k = 0; k < Dd; k++) {
            float wv = W2[k * Dd + tid];
            #pragma unroll
            for (int bb = 0; bb < NB; bb++) m2[bb] += S.er[bb][k] * wv;
        }
        __syncthreads();
        #pragma unroll
        for (int bb = 0; bb < NB; bb++)
            S.q[bb][tid] = (S.q[bb][tid] + m2[bb]) * INV_SQRT_DH;
    } else {
        #pragma unroll
        for (int bb = 0; bb < NB; bb++) S.q[bb][tid] *= INV_SQRT_DH;
    }
    __syncthreads();
}

__global__ void __launch_bounds__(256, 4) k4_decode(const float* __restrict__ E,
                                                    const float* __restrict__ coords,
                                                    const float* __restrict__ Ws,
                                                    const float* __restrict__ W1,
                                                    const float* __restrict__ b1,
                                                    const float* __restrict__ W2,
                                                    const float* __restrict__ b2,
                                                    float* __restrict__ out)
{
    extern __shared__ char smem_raw[];
    K4Smem& S = *(K4Smem*)smem_raw;

    const int b0 = blockIdx.x * NB;
    const int tid = threadIdx.x;
    const int warp = tid >> 5, lane = tid & 31;
    const int wb  = warp >> 2;
    const int wj0 = warp & 3;
    const int mlp = g_mlp;

    if (tid < Nn) {
        #pragma unroll
        for (int bb = 0; bb < NB; bb++) S.list[bb][tid] = tid;
    }
    if (tid == 0) S.cnt = Nn;
    #pragma unroll
    for (int bb = 0; bb < NB; bb++)
        S.q[bb][tid] = g_q0[(b0 + bb) * Dd + tid];
    k4_finalize_q(S, tid, mlp, W1, b1, W2, b2);

    const float* Kbase  = g_K   + (size_t)b0 * Nn * Dd;
    const float* Vbase  = g_V   + (size_t)b0 * Nn * Dd;
    const float* LKbase = g_LK2 + (size_t)b0 * Nn * Dd;

    float ll = 0.f, cost = 0.f;
    float fx = 0.f, fy = 0.f, px = 0.f, py = 0.f;
    float fctx[NB] = {0.f, 0.f};

    for (int t = 0; t < Nn; t++) {
        const int cnt = S.cnt;

        {
            const float4* q4 = (const float4*)S.q[wb];
            float4 qa = q4[lane], qb = q4[lane + 32];
            const float* Kb = Kbase + (size_t)wb * Nn * Dd;
            const int* lst = S.list[wb];
            for (int j = wj0; j < cnt; j += 4) {
                const float4* Kr = (const float4*)(Kb + (size_t)lst[j] * Dd);
                float4 k0 = __ldcg(Kr + lane);
                float4 k1 = __ldcg(Kr + lane + 32);
                float alo = k0.x * qa.x + k0.y * qa.y + k0.z * qa.z + k0.w * qa.w;
                float ahi = k1.x * qb.x + k1.y * qb.y + k1.z * qb.z + k1.w * qb.w;
                #pragma unroll
                for (int o = 1; o < 8; o <<= 1) {
                    alo += __shfl_xor_sync(0xffffffffu, alo, o);
                    ahi += __shfl_xor_sync(0xffffffffu, ahi, o);
                }
                if ((lane & 7) == 0) {
                    int hg = lane >> 3;
                    S.cc[wb][j][hg]     = alo;
                    S.cc[wb][j][4 + hg] = ahi;
                }
            }
        }
        __syncthreads();

        {
            const int h = warp;
            #pragma unroll
            for (int bb = 0; bb < NB; bb++) {
                float m = NEGV;
                for (int j = lane; j < cnt; j += 32) m = fmaxf(m, S.cc[bb][j][h]);
                #pragma unroll
                for (int o = 16; o; o >>= 1)
                    m = fmaxf(m, __shfl_xor_sync(0xffffffffu, m, o));
                float s = 0.f;
                for (int j = lane; j < cnt; j += 32) {
                    float e = expf(S.cc[bb][j][h] - m);
                    S.pp[bb][h][j] = e;
                    s += e;
                }
                #pragma unroll
                for (int o = 16; o; o >>= 1) s += __shfl_xor_sync(0xffffffffu, s, o);
                if (lane == 0) S.sum[bb][h] = s;
            }
        }
        __syncthreads();

        {
            const int d = tid, h = tid >> 5;
            float a[NB] = {0.f, 0.f};
            const float* Vd = Vbase + d;
            #pragma unroll 2
            for (int j = 0; j < cnt; j++) {
                #pragma unroll
                for (int bb = 0; bb < NB; bb++)
                    a[bb] += S.pp[bb][h][j] *
                             __ldcg(Vd + ((size_t)bb * Nn + S.list[bb][j]) * Dd);
            }
            #pragma unroll
            for (int bb = 0; bb < NB; bb++)
                S.heads[bb][d] = a[bb] / S.sum[bb][h];
        }
        __syncthreads();

        {
            const float4* h4 = (const float4*)S.heads[wb];
            float4 ha = h4[lane], hb = h4[lane + 32];
            const float* Lb = LKbase + (size_t)wb * Nn * Dd;
            const int* lst = S.list[wb];
            for (int j = wj0; j < cnt; j += 4) {
                const float4* Lr = (const float4*)(Lb + (size_t)lst[j] * Dd);
                float4 l0 = __ldcg(Lr + lane);
                float4 l1 = __ldcg(Lr + lane + 32);
                float a = l0.x * ha.x + l0.y * ha.y + l0.z * ha.z + l0.w * ha.w
                        + l1.x * hb.x + l1.y * hb.y + l1.z * hb.z + l1.w * hb.w;
                #pragma unroll
                for (int o = 16; o; o >>= 1) a += __shfl_xor_sync(0xffffffffu, a, o);
                if (lane == 0) S.ls[wb][j] = CLIPV * tanhf(a * INV_SQRT_D);
            }
        }
        __syncthreads();

        if (warp < NB) {
            const int bb = warp;
            float m = NEGV; int mj = 0;
            for (int j = lane; j < cnt; j += 32) {
                float v = S.ls[bb][j];
                if (v > m) { m = v; mj = j; }
            }
            #pragma unroll
            for (int o = 16; o; o >>= 1) {
                float vm = __shfl_xor_sync(0xffffffffu, m, o);
                int   vj = __shfl_xor_sync(0xffffffffu, mj, o);
                if (vm > m || (vm == m && vj < mj)) { m = vm; mj = vj; }
            }
            float s = 0.f;
            for (int j = lane; j < cnt; j += 32) s += expf(S.ls[bb][j] - m);
            #pragma unroll
            for (int o = 16; o; o >>= 1) s += __shfl_xor_sync(0xffffffffu, s, o);
            if (lane == 0) {
                int node = S.list[bb][mj];
                S.sel[bb] = node;
                ll += S.ls[bb][mj] - (m + logf(s));
                float cx = coords[((size_t)(b0 + bb) * Nn + node) * 2 + 0];
                float cy = coords[((size_t)(b0 + bb) * Nn + node) * 2 + 1];
                if (t == 0) { fx = cx; fy = cy; }
                else {
                    float dx = cx - px, dy = cy - py;
                    cost += sqrtf(dx * dx + dy * dy);
                }
                px = cx; py = cy;
                S.list[bb][mj] = S.list[bb][cnt - 1];
            }
        }
        if (tid == 0) S.cnt = cnt - 1;
        __syncthreads();

        if (t == 0) {
            #pragma unroll
            for (int bb = 0; bb < NB; bb++)
                S.er[bb][tid] =
                    E[((size_t)(b0 + bb) * Nn + S.sel[bb]) * Dd + tid];
            __syncthreads();
            float f[NB] = {0.f, 0.f};
            #pragma unroll 8
            for (int k = 0; k < Dd; k++) {
                float wv = Ws[k * Dd + tid];
                #pragma unroll
                for (int bb = 0; bb < NB; bb++) f[bb] += S.er[bb][k] * wv;
            }
            #pragma unroll
            for (int bb = 0; bb < NB; bb++) fctx[bb] = f[bb];
            __syncthreads();
        }

        if (t < Nn - 1) {
            float base[NB];
            #pragma unroll
            for (int bb = 0; bb < NB; bb++)
                base[bb] = fctx[bb] +
                    __ldcg(&g_P[((size_t)(b0 + bb) * Nn + S.sel[bb]) * Dd + tid]);
            float a0 = 0.f, a1 = 0.f, b0a = 0.f, b1a = 0.f;
            const float* Wp = g_Woc + tid;
            #pragma unroll 8
            for (int k = 0; k < Dd; k += 2) {
                float wv0 = Wp[(size_t)k * Dd];
                float wv1 = Wp[(size_t)(k + 1) * Dd];
                a0  += S.heads[0][k]     * wv0;
                b0a += S.heads[1][k]     * wv0;
                a1  += S.heads[0][k + 1] * wv1;
                b1a += S.heads[1][k + 1] * wv1;
            }
            __syncthreads();
            S.q[0][tid] = base[0] + (a0 + a1);
            S.q[1][tid] = base[1] + (b0a + b1a);
            k4_finalize_q(S, tid, mlp, W1, b1, W2, b2);
        }
    }

    if (warp < NB && lane == 0) {
        float dx = px - fx, dy = py - fy;
        cost += sqrtf(dx * dx + dy * dy);
        out[b0 + warp]      = cost;
        out[Bq + b0 + warp] = ll;
    }
}

// ---------------- launcher ---------------------------------------------------
extern "C" void kernel_launch(void* const* d_in, const int* in_sizes, int n_in,
                              void* d_out, int out_size)
{
    const float* coords = (const float*)d_in[0];
    const float* E      = (const float*)d_in[1];
    const float* Wk     = (const float*)d_in[2];
    const float* Wv     = (const float*)d_in[3];
    const float* Wlk    = (const float*)d_in[4];
    const float* Wo     = (const float*)d_in[5];
    const float* Wc     = (const float*)d_in[6];
    const float* Ws     = (const float*)d_in[7];
    const float* Wph    = (const float*)d_in[8];
    const float* W1     = (const float*)d_in[9];
    const float* b1     = (const float*)d_in[10];
    const float* W2     = (const float*)d_in[11];
    const float* b2     = (const float*)d_in[12];
    float* out = (float*)d_out;

    const int k4_smem = (int)sizeof(K4Smem);
    cudaFuncSetAttribute(k4_decode, cudaFuncAttributeMaxDynamicSharedMemorySize,
                         k4_smem);
    cudaFuncSetAttribute(k3t_mma, cudaFuncAttributeMaxDynamicSharedMemorySize,
                         K3T_SMEM);

    k0_prep<<<2, 256>>>(Wo, W2, b2);
    k1_weights<<<513, 256>>>(Wo, Wc, Wlk, Ws, Wph);
    k_splitE<<<8192, 256>>>(E);
    {
        dim3 gw(4, 256);
        k_splitW<<<gw, 256>>>(Wk, Wv, Ws);
    }
    k2_q0<<<Bq, 256>>>(E, Wc);
    {
        dim3 g3(ROWS_TOTAL / 128, 2, 4);
        k3t_mma<<<g3, 256, K3T_SMEM>>>();
    }
    k4_decode<<<Bq / NB, 256, k4_smem>>>(E, coords, Ws, W1, b1, W2, b2, out);
}

// round 9
// speedup vs baseline: 1.0604x; 1.0604x over previous
#include <cuda_runtime.h>
#include <cuda_bf16.h>
#include <cstdint>

// Problem constants
#define Bq   1024
#define Nn   128
#define Dd   256
#define Hh   8
#define NB   2
#define NEGV (-1e9f)
#define CLIPV 10.0f
#define INV_SQRT_DH 0.17677669529663687f  // 1/sqrt(32)
#define INV_SQRT_D  0.0625f               // 1/sqrt(256)

#define ROWS_TOTAL (Bq * Nn)              // 131072

// ---------------- scratch (device globals; no cudaMalloc allowed) ----------
__device__ float g_K   [Bq * Nn * Dd];   // [b][n][d]  (E@Wk)
__device__ float g_V   [Bq * Nn * Dd];   // [b][n][d]  (E@Wv)
__device__ float g_LK2 [Bq * Nn * Dd];   // [b][n][d]  (E@(Wlk@Wo^T))
__device__ float g_P   [Bq * Nn * Dd];   // [b][n][d]  (E@Ws_bot)
__device__ float g_q0  [Bq * Dd];        // step-0 query (pre-MLP)
__device__ float g_Woc [Dd * Dd];        // Wo@Wc
__device__ float g_Wlk2[Dd * Dd];        // Wlk@Wo^T
__device__ float g_WoT [Dd * Dd];        // Wo^T
__device__ float g_pc  [Dd];             // W_placeholder @ Ws
__device__ int   g_mlp;                  // 1 if (W2,b2) nonzero -> general path

// bf16 3-way exact splits (x = s0+s1+s2 exactly for fp32 inputs)
__device__ __nv_bfloat16 g_Es[3][ROWS_TOTAL * Dd];     // E splits
__device__ __nv_bfloat16 g_Wt[3][4][Dd * Dd];          // W^T splits [s][w][n][k]

// ================= helpers ==================================================
__device__ __forceinline__ uint32_t smem_u32(const void* p) {
    uint32_t a;
    asm("{ .reg .u64 t; cvta.to.shared.u64 t, %1; cvt.u32.u64 %0, t; }"
        : "=r"(a) : "l"(p));
    return a;
}
#define SW128(x) ((x) ^ (((x) >> 3) & 0x70))

__device__ __forceinline__ void ldsm_x4(uint32_t* r, uint32_t addr) {
    asm volatile("ldmatrix.sync.aligned.m8n8.x4.shared.b16 {%0,%1,%2,%3}, [%4];"
        : "=r"(r[0]), "=r"(r[1]), "=r"(r[2]), "=r"(r[3]) : "r"(addr));
}
__device__ __forceinline__ void ldsm_x2(uint32_t* r, uint32_t addr) {
    asm volatile("ldmatrix.sync.aligned.m8n8.x2.shared.b16 {%0,%1}, [%2];"
        : "=r"(r[0]), "=r"(r[1]) : "r"(addr));
}
__device__ __forceinline__ void mma_bf16(float* c, const uint32_t* a, const uint32_t* b) {
    asm volatile("mma.sync.aligned.m16n8k16.row.col.f32.bf16.bf16.f32 "
        "{%0,%1,%2,%3}, {%4,%5,%6,%7}, {%8,%9}, {%0,%1,%2,%3};"
        : "+f"(c[0]), "+f"(c[1]), "+f"(c[2]), "+f"(c[3])
        : "r"(a[0]), "r"(a[1]), "r"(a[2]), "r"(a[3]), "r"(b[0]), "r"(b[1]));
}

// ---------------- k0: transpose Wo, detect MLP-nonzero ---------------------
__global__ void k0_prep(const float* __restrict__ Wo,
                        const float* __restrict__ W2,
                        const float* __restrict__ b2)
{
    if (blockIdx.x == 0) {
        for (int i = threadIdx.x; i < Dd * Dd; i += blockDim.x) {
            int k = i >> 8, d = i & 255;
            g_WoT[d * Dd + k] = Wo[k * Dd + d];
        }
    } else {
        __shared__ int any;
        if (threadIdx.x == 0) any = 0;
        __syncthreads();
        int loc = 0;
        for (int i = threadIdx.x; i < Dd * Dd; i += blockDim.x)
            loc |= (W2[i] != 0.0f);
        if (threadIdx.x < Dd) loc |= (b2[threadIdx.x] != 0.0f);
        if (loc) atomicOr(&any, 1);
        __syncthreads();
        if (threadIdx.x == 0) g_mlp = any;
    }
}

// ---------------- k1: Woc = Wo@Wc ; Wlk2 = Wlk@Wo^T ; pc = placeholder@Ws --
__global__ void k1_weights(const float* __restrict__ Wo,
                           const float* __restrict__ Wc,
                           const float* __restrict__ Wlk,
                           const float* __restrict__ Ws,
                           const float* __restrict__ Wph)
{
    int bid = blockIdx.x;
    int d = threadIdx.x;
    if (bid < 256) {
        float acc = 0.f;
        #pragma unroll 8
        for (int j = 0; j < Dd; j++) acc += Wo[bid * Dd + j] * Wc[j * Dd + d];
        g_Woc[bid * Dd + d] = acc;
    } else if (bid < 512) {
        int m = bid - 256;
        float acc = 0.f;
        #pragma unroll 8
        for (int j = 0; j < Dd; j++) acc += Wlk[m * Dd + j] * g_WoT[j * Dd + d];
        g_Wlk2[m * Dd + d] = acc;
    } else {
        float acc = 0.f;
        #pragma unroll 8
        for (int k = 0; k < 2 * Dd; k++) acc += Wph[k] * Ws[k * Dd + d];
        g_pc[d] = acc;
    }
}

// ---------------- k2: q0 = mean_n(E) @ Wc + pc ------------------------------
__global__ void k2_q0(const float* __restrict__ E, const float* __restrict__ Wc)
{
    int b = blockIdx.x, d = threadIdx.x;
    __shared__ float g[Dd];
    float s = 0.f;
    const float* Eb = E + (size_t)b * Nn * Dd + d;
    #pragma unroll 8
    for (int n = 0; n < Nn; n++) s += Eb[n * Dd];
    g[d] = s * (1.0f / Nn);
    __syncthreads();
    float acc = g_pc[d];
    #pragma unroll 8
    for (int k = 0; k < Dd; k++) acc += g[k] * Wc[k * Dd + d];
    g_q0[b * Dd + d] = acc;
}

// ---------------- split kernels: exact fp32 -> 3x bf16 ----------------------
__global__ void k_splitE(const float* __restrict__ E)
{
    const size_t total = (size_t)ROWS_TOTAL * Dd;
    const size_t stride = (size_t)gridDim.x * blockDim.x;
    for (size_t i = (size_t)blockIdx.x * blockDim.x + threadIdx.x; i < total; i += stride) {
        float x = E[i];
        __nv_bfloat16 s0 = __float2bfloat16_rn(x);
        float r = x - __bfloat162float(s0);
        __nv_bfloat16 s1 = __float2bfloat16_rn(r);
        float r2 = r - __bfloat162float(s1);
        __nv_bfloat16 s2 = __float2bfloat16_rn(r2);
        g_Es[0][i] = s0; g_Es[1][i] = s1; g_Es[2][i] = s2;
    }
}

// transposed weight splits: g_Wt[s][w][n*256+k] = split_s(W_w[k][n])
__global__ void k_splitW(const float* __restrict__ Wk,
                         const float* __restrict__ Wv,
                         const float* __restrict__ Ws)
{
    const int w = blockIdx.x, n = blockIdx.y, k = threadIdx.x;
    const float* src;
    if      (w == 0) src = Wk;
    else if (w == 1) src = Wv;
    else if (w == 2) src = g_Wlk2;
    else             src = Ws + Dd * Dd;
    float x = src[k * Dd + n];
    __nv_bfloat16 s0 = __float2bfloat16_rn(x);
    float r = x - __bfloat162float(s0);
    __nv_bfloat16 s1 = __float2bfloat16_rn(r);
    float r2 = r - __bfloat162float(s1);
    __nv_bfloat16 s2 = __float2bfloat16_rn(r2);
    g_Wt[0][w][n * Dd + k] = s0;
    g_Wt[1][w][n * Dd + k] = s1;
    g_Wt[2][w][n * Dd + k] = s2;
}

// ---------------- k3t: mma.sync bf16-3split GEMM  out = E @ W --------------
// CTA tile 128m x 128n, 8 warps (each 32m x 64n), K chunked x64.
// 6 split passes (sa+sb<=2): exact to ~2^-24.
// Regs capped for 2 CTA/SM co-residency (load/compute overlap across CTAs);
// swizzled ldmatrix addresses hoisted out of the inner loops.
static constexpr int K3_A_OFF = 0;
static constexpr int K3_B_OFF = 3 * 16384;
static constexpr int K3T_SMEM = 6 * 16384;   // 98304

__global__ void __launch_bounds__(256, 2) k3t_mma()
{
    extern __shared__ char smem[];
    const uint32_t sbase = smem_u32(smem);
    const int tid = threadIdx.x;
    const int warp = tid >> 5, lane = tid & 31;
    const int rowbase = blockIdx.x * 128;
    const int nbase   = blockIdx.y * 128;
    const int w       = blockIdx.z;

    float* out;
    if      (w == 0) out = g_K;
    else if (w == 1) out = g_V;
    else if (w == 2) out = g_LK2;
    else             out = g_P;

    const int wm = warp & 3;      // 4 m-blocks of 32 rows
    const int wn = warp >> 2;     // 2 n-blocks of 64 cols

    float acc[2][8][4] = {};      // [mblk16][nblk8][frag]

    // Hoisted ldmatrix addressing:
    // SW128(row*128 + koff) = row*128 + (koff ^ ((row&7)<<4)), and
    // koff = ks*32 | kb0 (disjoint bits) -> addr = base + (ks*32 ^ kmask).
    uint32_t a_base[2], a_kmask[2];
    #pragma unroll
    for (int mb = 0; mb < 2; mb++) {
        int row = wm * 32 + mb * 16 + (lane & 15);
        a_base[mb]  = sbase + K3_A_OFF + (uint32_t)row * 128;
        a_kmask[mb] = (uint32_t)(((row & 7) << 4) ^ ((lane >> 4) * 16));
    }
    uint32_t b_base[8], b_kmask[8];
    #pragma unroll
    for (int nb = 0; nb < 8; nb++) {
        int row = wn * 64 + nb * 8 + (lane & 7);
        b_base[nb]  = sbase + K3_B_OFF + (uint32_t)row * 128;
        b_kmask[nb] = (uint32_t)(((row & 7) << 4) ^ (((lane >> 3) & 1) * 16));
    }

    for (int c = 0; c < 4; c++) {
        // ---- stage A splits: [3][128 rows][64 bf16] SW128 ------------------
        for (int i = tid; i < 3072; i += 256) {
            int s = i >> 10, rem = i & 1023;
            int row = rem >> 3, q = rem & 7;
            uint4 v = *(const uint4*)(&g_Es[s][(size_t)(rowbase + row) * Dd + c * 64 + q * 8]);
            *(uint4*)(smem + K3_A_OFF + s * 16384 + SW128(row * 128 + q * 16)) = v;
        }
        // ---- stage B splits: [3][128 n][64 k bf16] SW128 -------------------
        for (int i = tid; i < 3072; i += 256) {
            int s = i >> 10, rem = i & 1023;
            int n = rem >> 3, q = rem & 7;
            uint4 v = *(const uint4*)(&g_Wt[s][w][(size_t)(nbase + n) * Dd + c * 64 + q * 8]);
            *(uint4*)(smem + K3_B_OFF + s * 16384 + SW128(n * 128 + q * 16)) = v;
        }
        __syncthreads();

        #pragma unroll
        for (int ks = 0; ks < 4; ks++) {
            const uint32_t kx = (uint32_t)(ks * 32);
            // A fragments: 3 splits x 2 m-blocks (24 regs)
            uint32_t af[3][2][4];
            #pragma unroll
            for (int s = 0; s < 3; s++)
                #pragma unroll
                for (int mb = 0; mb < 2; mb++)
                    ldsm_x4(af[s][mb], a_base[mb] + s * 16384 + (kx ^ a_kmask[mb]));
            // B fragment scoped per (sb, nb): only 2 regs live
            #pragma unroll
            for (int sb = 0; sb < 3; sb++) {
                #pragma unroll
                for (int nb = 0; nb < 8; nb++) {
                    uint32_t bf[2];
                    ldsm_x2(bf, b_base[nb] + sb * 16384 + (kx ^ b_kmask[nb]));
                    #pragma unroll
                    for (int sa = 0; sa <= 2 - sb; sa++) {
                        mma_bf16(acc[0][nb], af[sa][0], bf);
                        mma_bf16(acc[1][nb], af[sa][1], bf);
                    }
                }
            }
        }
        __syncthreads();
    }

    // ---- epilogue: fp32 stores -------------------------------------------
    const int r0 = rowbase + wm * 32 + (lane >> 2);
    const int c0 = nbase + wn * 64 + (lane & 3) * 2;
    #pragma unroll
    for (int mb = 0; mb < 2; mb++)
        #pragma unroll
        for (int nb = 0; nb < 8; nb++) {
            float2 lo = make_float2(acc[mb][nb][0], acc[mb][nb][1]);
            float2 hi = make_float2(acc[mb][nb][2], acc[mb][nb][3]);
            *(float2*)(out + (size_t)(r0 + mb * 16)     * Dd + c0 + nb * 8) = lo;
            *(float2*)(out + (size_t)(r0 + mb * 16 + 8) * Dd + c0 + nb * 8) = hi;
        }
}

// ---------------- k4: persistent decode, NB=2 batches per block -------------
struct K4Smem {
    float q[NB][Dd];
    float heads[NB][Dd];
    float cc[NB][Nn][9];
    float pp[NB][Hh][Nn + 4];
    float ls[NB][Nn];
    int   list[NB][Nn];
    float er[NB][Dd];
    float sum[NB][Hh];
    int   sel[NB];
    int   cnt;
};

__device__ __forceinline__ void k4_finalize_q(K4Smem& S, int tid, int mlp,
                                              const float* __restrict__ W1,
                                              const float* __restrict__ b1,
                                              const float* __restrict__ W2,
                                              const float* __restrict__ b2)
{
    if (mlp) {
        __syncthreads();
        float m1[NB];
        #pragma unroll
        for (int bb = 0; bb < NB; bb++) m1[bb] = b1[tid];
        #pragma unroll 8
        for (int k = 0; k < Dd; k++) {
            float wv = W1[k * Dd + tid];
            #pragma unroll
            for (int bb = 0; bb < NB; bb++) m1[bb] += S.q[bb][k] * wv;
        }
        #pragma unroll
        for (int bb = 0; bb < NB; bb++) S.er[bb][tid] = fmaxf(m1[bb], 0.0f);
        __syncthreads();
        float m2[NB];
        #pragma unroll
        for (int bb = 0; bb < NB; bb++) m2[bb] = b2[tid];
        #pragma unroll 8
        for (int k = 0; k < Dd; k++) {
            float wv = W2[k * Dd + tid];
            #pragma unroll
            for (int bb = 0; bb < NB; bb++) m2[bb] += S.er[bb][k] * wv;
        }
        __syncthreads();
        #pragma unroll
        for (int bb = 0; bb < NB; bb++)
            S.q[bb][tid] = (S.q[bb][tid] + m2[bb]) * INV_SQRT_DH;
    } else {
        #pragma unroll
        for (int bb = 0; bb < NB; bb++) S.q[bb][tid] *= INV_SQRT_DH;
    }
    __syncthreads();
}

__global__ void __launch_bounds__(256, 4) k4_decode(const float* __restrict__ E,
                                                    const float* __restrict__ coords,
                                                    const float* __restrict__ Ws,
                                                    const float* __restrict__ W1,
                                                    const float* __restrict__ b1,
                                                    const float* __restrict__ W2,
                                                    const float* __restrict__ b2,
                                                    float* __restrict__ out)
{
    extern __shared__ char smem_raw[];
    K4Smem& S = *(K4Smem*)smem_raw;

    const int b0 = blockIdx.x * NB;
    const int tid = threadIdx.x;
    const int warp = tid >> 5, lane = tid & 31;
    const int wb  = warp >> 2;
    const int wj0 = warp & 3;
    const int mlp = g_mlp;

    if (tid < Nn) {
        #pragma unroll
        for (int bb = 0; bb < NB; bb++) S.list[bb][tid] = tid;
    }
    if (tid == 0) S.cnt = Nn;
    #pragma unroll
    for (int bb = 0; bb < NB; bb++)
        S.q[bb][tid] = g_q0[(b0 + bb) * Dd + tid];
    k4_finalize_q(S, tid, mlp, W1, b1, W2, b2);

    const float* Kbase  = g_K   + (size_t)b0 * Nn * Dd;
    const float* Vbase  = g_V   + (size_t)b0 * Nn * Dd;
    const float* LKbase = g_LK2 + (size_t)b0 * Nn * Dd;

    float ll = 0.f, cost = 0.f;
    float fx = 0.f, fy = 0.f, px = 0.f, py = 0.f;
    float fctx[NB] = {0.f, 0.f};

    for (int t = 0; t < Nn; t++) {
        const int cnt = S.cnt;

        {
            const float4* q4 = (const float4*)S.q[wb];
            float4 qa = q4[lane], qb = q4[lane + 32];
            const float* Kb = Kbase + (size_t)wb * Nn * Dd;
            const int* lst = S.list[wb];
            for (int j = wj0; j < cnt; j += 4) {
                const float4* Kr = (const float4*)(Kb + (size_t)lst[j] * Dd);
                float4 k0 = __ldcg(Kr + lane);
                float4 k1 = __ldcg(Kr + lane + 32);
                float alo = k0.x * qa.x + k0.y * qa.y + k0.z * qa.z + k0.w * qa.w;
                float ahi = k1.x * qb.x + k1.y * qb.y + k1.z * qb.z + k1.w * qb.w;
                #pragma unroll
                for (int o = 1; o < 8; o <<= 1) {
                    alo += __shfl_xor_sync(0xffffffffu, alo, o);
                    ahi += __shfl_xor_sync(0xffffffffu, ahi, o);
                }
                if ((lane & 7) == 0) {
                    int hg = lane >> 3;
                    S.cc[wb][j][hg]     = alo;
                    S.cc[wb][j][4 + hg] = ahi;
                }
            }
        }
        __syncthreads();

        {
            const int h = warp;
            #pragma unroll
            for (int bb = 0; bb < NB; bb++) {
                float m = NEGV;
                for (int j = lane; j < cnt; j += 32) m = fmaxf(m, S.cc[bb][j][h]);
                #pragma unroll
                for (int o = 16; o; o >>= 1)
                    m = fmaxf(m, __shfl_xor_sync(0xffffffffu, m, o));
                float s = 0.f;
                for (int j = lane; j < cnt; j += 32) {
                    float e = expf(S.cc[bb][j][h] - m);
                    S.pp[bb][h][j] = e;
                    s += e;
                }
                #pragma unroll
                for (int o = 16; o; o >>= 1) s += __shfl_xor_sync(0xffffffffu, s, o);
                if (lane == 0) S.sum[bb][h] = s;
            }
        }
        __syncthreads();

        {
            const int d = tid, h = tid >> 5;
            float a[NB] = {0.f, 0.f};
            const float* Vd = Vbase + d;
            #pragma unroll 2
            for (int j = 0; j < cnt; j++) {
                #pragma unroll
                for (int bb = 0; bb < NB; bb++)
                    a[bb] += S.pp[bb][h][j] *
                             __ldcg(Vd + ((size_t)bb * Nn + S.list[bb][j]) * Dd);
            }
            #pragma unroll
            for (int bb = 0; bb < NB; bb++)
                S.heads[bb][d] = a[bb] / S.sum[bb][h];
        }
        __syncthreads();

        {
            const float4* h4 = (const float4*)S.heads[wb];
            float4 ha = h4[lane], hb = h4[lane + 32];
            const float* Lb = LKbase + (size_t)wb * Nn * Dd;
            const int* lst = S.list[wb];
            for (int j = wj0; j < cnt; j += 4) {
                const float4* Lr = (const float4*)(Lb + (size_t)lst[j] * Dd);
                float4 l0 = __ldcg(Lr + lane);
                float4 l1 = __ldcg(Lr + lane + 32);
                float a = l0.x * ha.x + l0.y * ha.y + l0.z * ha.z + l0.w * ha.w
                        + l1.x * hb.x + l1.y * hb.y + l1.z * hb.z + l1.w * hb.w;
                #pragma unroll
                for (int o = 16; o; o >>= 1) a += __shfl_xor_sync(0xffffffffu, a, o);
                if (lane == 0) S.ls[wb][j] = CLIPV * tanhf(a * INV_SQRT_D);
            }
        }
        __syncthreads();

        if (warp < NB) {
            const int bb = warp;
            float m = NEGV; int mj = 0;
            for (int j = lane; j < cnt; j += 32) {
                float v = S.ls[bb][j];
                if (v > m) { m = v; mj = j; }
            }
            #pragma unroll
            for (int o = 16; o; o >>= 1) {
                float vm = __shfl_xor_sync(0xffffffffu, m, o);
                int   vj = __shfl_xor_sync(0xffffffffu, mj, o);
                if (vm > m || (vm == m && vj < mj)) { m = vm; mj = vj; }
            }
            float s = 0.f;
            for (int j = lane; j < cnt; j += 32) s += expf(S.ls[bb][j] - m);
            #pragma unroll
            for (int o = 16; o; o >>= 1) s += __shfl_xor_sync(0xffffffffu, s, o);
            if (lane == 0) {
                int node = S.list[bb][mj];
                S.sel[bb] = node;
                ll += S.ls[bb][mj] - (m + logf(s));
                float cx = coords[((size_t)(b0 + bb) * Nn + node) * 2 + 0];
                float cy = coords[((size_t)(b0 + bb) * Nn + node) * 2 + 1];
                if (t == 0) { fx = cx; fy = cy; }
                else {
                    float dx = cx - px, dy = cy - py;
                    cost += sqrtf(dx * dx + dy * dy);
                }
                px = cx; py = cy;
                S.list[bb][mj] = S.list[bb][cnt - 1];
            }
        }
        if (tid == 0) S.cnt = cnt - 1;
        __syncthreads();

        if (t == 0) {
            #pragma unroll
            for (int bb = 0; bb < NB; bb++)
                S.er[bb][tid] =
                    E[((size_t)(b0 + bb) * Nn + S.sel[bb]) * Dd + tid];
            __syncthreads();
            float f[NB] = {0.f, 0.f};
            #pragma unroll 8
            for (int k = 0; k < Dd; k++) {
                float wv = Ws[k * Dd + tid];
                #pragma unroll
                for (int bb = 0; bb < NB; bb++) f[bb] += S.er[bb][k] * wv;
            }
            #pragma unroll
            for (int bb = 0; bb < NB; bb++) fctx[bb] = f[bb];
            __syncthreads();
        }

        if (t < Nn - 1) {
            float base[NB];
            #pragma unroll
            for (int bb = 0; bb < NB; bb++)
                base[bb] = fctx[bb] +
                    __ldcg(&g_P[((size_t)(b0 + bb) * Nn + S.sel[bb]) * Dd + tid]);
            float a0 = 0.f, a1 = 0.f, b0a = 0.f, b1a = 0.f;
            const float* Wp = g_Woc + tid;
            #pragma unroll 8
            for (int k = 0; k < Dd; k += 2) {
                float wv0 = Wp[(size_t)k * Dd];
                float wv1 = Wp[(size_t)(k + 1) * Dd];
                a0  += S.heads[0][k]     * wv0;
                b0a += S.heads[1][k]     * wv0;
                a1  += S.heads[0][k + 1] * wv1;
                b1a += S.heads[1][k + 1] * wv1;
            }
            __syncthreads();
            S.q[0][tid] = base[0] + (a0 + a1);
            S.q[1][tid] = base[1] + (b0a + b1a);
            k4_finalize_q(S, tid, mlp, W1, b1, W2, b2);
        }
    }

    if (warp < NB && lane == 0) {
        float dx = px - fx, dy = py - fy;
        cost += sqrtf(dx * dx + dy * dy);
        out[b0 + warp]      = cost;
        out[Bq + b0 + warp] = ll;
    }
}

// ---------------- launcher ---------------------------------------------------
extern "C" void kernel_launch(void* const* d_in, const int* in_sizes, int n_in,
                              void* d_out, int out_size)
{
    const float* coords = (const float*)d_in[0];
    const float* E      = (const float*)d_in[1];
    const float* Wk     = (const float*)d_in[2];
    const float* Wv     = (const float*)d_in[3];
    const float* Wlk    = (const float*)d_in[4];
    const float* Wo     = (const float*)d_in[5];
    const float* Wc     = (const float*)d_in[6];
    const float* Ws     = (const float*)d_in[7];
    const float* Wph    = (const float*)d_in[8];
    const float* W1     = (const float*)d_in[9];
    const float* b1     = (const float*)d_in[10];
    const float* W2     = (const float*)d_in[11];
    const float* b2     = (const float*)d_in[12];
    float* out = (float*)d_out;

    const int k4_smem = (int)sizeof(K4Smem);
    cudaFuncSetAttribute(k4_decode, cudaFuncAttributeMaxDynamicSharedMemorySize,
                         k4_smem);
    cudaFuncSetAttribute(k3t_mma, cudaFuncAttributeMaxDynamicSharedMemorySize,
                         K3T_SMEM);

    k0_prep<<<2, 256>>>(Wo, W2, b2);
    k1_weights<<<513, 256>>>(Wo, Wc, Wlk, Ws, Wph);
    k_splitE<<<8192, 256>>>(E);
    {
        dim3 gw(4, 256);
        k_splitW<<<gw, 256>>>(Wk, Wv, Ws);
    }
    k2_q0<<<Bq, 256>>>(E, Wc);
    {
        dim3 g3(ROWS_TOTAL / 128, 2, 4);
        k3t_mma<<<g3, 256, K3T_SMEM>>>();
    }
    k4_decode<<<Bq / NB, 256, k4_smem>>>(E, coords, Ws, W1, b1, W2, b2, out);
}

// round 10
// speedup vs baseline: 1.1172x; 1.0535x over previous
#include <cuda_runtime.h>
#include <cuda_fp16.h>
#include <cstdint>

// Problem constants
#define Bq   1024
#define Nn   128
#define Dd   256
#define Hh   8
#define NB   2
#define NEGV (-1e9f)
#define CLIPV 10.0f
#define INV_SQRT_DH 0.17677669529663687f  // 1/sqrt(32)
#define INV_SQRT_D  0.0625f               // 1/sqrt(256)

#define ROWS_TOTAL (Bq * Nn)              // 131072
#define WSCALE     16.0f                  // W pre-scale (exact pow2)
#define WUNSCALE   0.0625f                // 1/16

// ---------------- scratch (device globals; no cudaMalloc allowed) ----------
__device__ float g_K   [Bq * Nn * Dd];   // [b][n][d]  (E@Wk)
__device__ float g_V   [Bq * Nn * Dd];   // [b][n][d]  (E@Wv)
__device__ float g_LK2 [Bq * Nn * Dd];   // [b][n][d]  (E@(Wlk@Wo^T))
__device__ float g_P   [Bq * Nn * Dd];   // [b][n][d]  (E@Ws_bot)
__device__ float g_q0  [Bq * Dd];        // step-0 query (pre-MLP)
__device__ float g_Woc [Dd * Dd];        // Wo@Wc
__device__ float g_Wlk2[Dd * Dd];        // Wlk@Wo^T
__device__ float g_WoT [Dd * Dd];        // Wo^T
__device__ float g_pc  [Dd];             // W_placeholder @ Ws
__device__ int   g_mlp;                  // 1 if (W2,b2) nonzero -> general path

// fp16 2-way splits (x ~= h0+h1 to ~2^-22)
__device__ __half g_Es[2][ROWS_TOTAL * Dd];     // E splits
__device__ __half g_Wt[2][4][Dd * Dd];          // (16*W)^T splits [s][w][n][k]

// ================= helpers ==================================================
__device__ __forceinline__ uint32_t smem_u32(const void* p) {
    uint32_t a;
    asm("{ .reg .u64 t; cvta.to.shared.u64 t, %1; cvt.u32.u64 %0, t; }"
        : "=r"(a) : "l"(p));
    return a;
}
#define SW128(x) ((x) ^ (((x) >> 3) & 0x70))

__device__ __forceinline__ void ldsm_x4(uint32_t* r, uint32_t addr) {
    asm volatile("ldmatrix.sync.aligned.m8n8.x4.shared.b16 {%0,%1,%2,%3}, [%4];"
        : "=r"(r[0]), "=r"(r[1]), "=r"(r[2]), "=r"(r[3]) : "r"(addr));
}
__device__ __forceinline__ void mma_fp16(float* c, const uint32_t* a, const uint32_t* b) {
    asm volatile("mma.sync.aligned.m16n8k16.row.col.f32.f16.f16.f32 "
        "{%0,%1,%2,%3}, {%4,%5,%6,%7}, {%8,%9}, {%0,%1,%2,%3};"
        : "+f"(c[0]), "+f"(c[1]), "+f"(c[2]), "+f"(c[3])
        : "r"(a[0]), "r"(a[1]), "r"(a[2]), "r"(a[3]), "r"(b[0]), "r"(b[1]));
}

// ---------------- k0: transpose Wo, detect MLP-nonzero ---------------------
__global__ void k0_prep(const float* __restrict__ Wo,
                        const float* __restrict__ W2,
                        const float* __restrict__ b2)
{
    if (blockIdx.x == 0) {
        for (int i = threadIdx.x; i < Dd * Dd; i += blockDim.x) {
            int k = i >> 8, d = i & 255;
            g_WoT[d * Dd + k] = Wo[k * Dd + d];
        }
    } else {
        __shared__ int any;
        if (threadIdx.x == 0) any = 0;
        __syncthreads();
        int loc = 0;
        for (int i = threadIdx.x; i < Dd * Dd; i += blockDim.x)
            loc |= (W2[i] != 0.0f);
        if (threadIdx.x < Dd) loc |= (b2[threadIdx.x] != 0.0f);
        if (loc) atomicOr(&any, 1);
        __syncthreads();
        if (threadIdx.x == 0) g_mlp = any;
    }
}

// ---------------- k1: Woc = Wo@Wc ; Wlk2 = Wlk@Wo^T ; pc = placeholder@Ws --
__global__ void k1_weights(const float* __restrict__ Wo,
                           const float* __restrict__ Wc,
                           const float* __restrict__ Wlk,
                           const float* __restrict__ Ws,
                           const float* __restrict__ Wph)
{
    int bid = blockIdx.x;
    int d = threadIdx.x;
    if (bid < 256) {
        float acc = 0.f;
        #pragma unroll 8
        for (int j = 0; j < Dd; j++) acc += Wo[bid * Dd + j] * Wc[j * Dd + d];
        g_Woc[bid * Dd + d] = acc;
    } else if (bid < 512) {
        int m = bid - 256;
        float acc = 0.f;
        #pragma unroll 8
        for (int j = 0; j < Dd; j++) acc += Wlk[m * Dd + j] * g_WoT[j * Dd + d];
        g_Wlk2[m * Dd + d] = acc;
    } else {
        float acc = 0.f;
        #pragma unroll 8
        for (int k = 0; k < 2 * Dd; k++) acc += Wph[k] * Ws[k * Dd + d];
        g_pc[d] = acc;
    }
}

// ---------------- k2: q0 = mean_n(E) @ Wc + pc ------------------------------
__global__ void k2_q0(const float* __restrict__ E, const float* __restrict__ Wc)
{
    int b = blockIdx.x, d = threadIdx.x;
    __shared__ float g[Dd];
    float s = 0.f;
    const float* Eb = E + (size_t)b * Nn * Dd + d;
    #pragma unroll 8
    for (int n = 0; n < Nn; n++) s += Eb[n * Dd];
    g[d] = s * (1.0f / Nn);
    __syncthreads();
    float acc = g_pc[d];
    #pragma unroll 8
    for (int k = 0; k < Dd; k++) acc += g[k] * Wc[k * Dd + d];
    g_q0[b * Dd + d] = acc;
}

// ---------------- split kernels: fp32 -> 2x fp16 (to ~2^-22) ----------------
__global__ void k_splitE(const float* __restrict__ E)
{
    const size_t total = (size_t)ROWS_TOTAL * Dd;
    const size_t stride = (size_t)gridDim.x * blockDim.x;
    for (size_t i = (size_t)blockIdx.x * blockDim.x + threadIdx.x; i < total; i += stride) {
        float x = E[i];
        __half h0 = __float2half_rn(x);
        float r = x - __half2float(h0);
        __half h1 = __float2half_rn(r);
        g_Es[0][i] = h0; g_Es[1][i] = h1;
    }
}

// transposed weight splits of 16*W (keeps h1 out of fp16 denormals):
// g_Wt[s][w][n*256+k] = split_s(16 * W_w[k][n])
__global__ void k_splitW(const float* __restrict__ Wk,
                         const float* __restrict__ Wv,
                         const float* __restrict__ Ws)
{
    const int w = blockIdx.x, n = blockIdx.y, k = threadIdx.x;
    const float* src;
    if      (w == 0) src = Wk;
    else if (w == 1) src = Wv;
    else if (w == 2) src = g_Wlk2;
    else             src = Ws + Dd * Dd;
    float x = src[k * Dd + n] * WSCALE;
    __half h0 = __float2half_rn(x);
    float r = x - __half2float(h0);
    __half h1 = __float2half_rn(r);
    g_Wt[0][w][n * Dd + k] = h0;
    g_Wt[1][w][n * Dd + k] = h1;
}

// ---------------- k3t: mma.sync fp16-2split GEMM  out = E @ W --------------
// CTA tile 128m x 128n, 8 warps (each 32m x 64n), K chunked x64.
// 3 split passes (00, 01, 10): error ~2^-22. Output unscaled by 1/16.
// smem: A 2x16KB + B 2x16KB = 64KB, SW128; 2 CTAs/SM co-resident.
static constexpr int K3_A_OFF = 0;
static constexpr int K3_B_OFF = 2 * 16384;
static constexpr int K3T_SMEM = 4 * 16384;   // 65536

__global__ void __launch_bounds__(256, 2) k3t_mma()
{
    extern __shared__ char smem[];
    const uint32_t sbase = smem_u32(smem);
    const int tid = threadIdx.x;
    const int warp = tid >> 5, lane = tid & 31;
    const int rowbase = blockIdx.x * 128;
    const int nbase   = blockIdx.y * 128;
    const int w       = blockIdx.z;

    float* out;
    if      (w == 0) out = g_K;
    else if (w == 1) out = g_V;
    else if (w == 2) out = g_LK2;
    else             out = g_P;

    const int wm = warp & 3;      // 4 m-blocks of 32 rows
    const int wn = warp >> 2;     // 2 n-blocks of 64 cols

    float acc[2][8][4] = {};      // [mblk16][nblk8][frag]

    // Hoisted swizzled addressing (koff = ks*32 | bits16 -> addr = base + (kx ^ kmask))
    uint32_t a_base[2], a_kmask[2];
    #pragma unroll
    for (int mb = 0; mb < 2; mb++) {
        int row = wm * 32 + mb * 16 + (lane & 15);
        a_base[mb]  = sbase + K3_A_OFF + (uint32_t)row * 128;
        a_kmask[mb] = (uint32_t)(((row & 7) << 4) ^ ((lane >> 4) * 16));
    }
    // B via paired ldmatrix.x4: matrices (nb,k0),(nb,k1),(nb+1,k0),(nb+1,k1)
    uint32_t b_base[4], b_kmask[4];
    #pragma unroll
    for (int p = 0; p < 4; p++) {
        int pr = lane >> 3;                         // matrix id 0..3
        int nrow = wn * 64 + p * 16 + ((pr >> 1) << 3) + (lane & 7);
        int khalf = pr & 1;
        b_base[p]  = sbase + K3_B_OFF + (uint32_t)nrow * 128;
        b_kmask[p] = (uint32_t)(((nrow & 7) << 4) ^ (khalf << 4));
    }

    for (int c = 0; c < 4; c++) {
        // ---- stage A splits: [2][128 rows][64 fp16] SW128 ------------------
        for (int i = tid; i < 2048; i += 256) {
            int s = i >> 10, rem = i & 1023;
            int row = rem >> 3, q = rem & 7;
            uint4 v = *(const uint4*)(&g_Es[s][(size_t)(rowbase + row) * Dd + c * 64 + q * 8]);
            *(uint4*)(smem + K3_A_OFF + s * 16384 + SW128(row * 128 + q * 16)) = v;
        }
        // ---- stage B splits: [2][128 n][64 k fp16] SW128 -------------------
        for (int i = tid; i < 2048; i += 256) {
            int s = i >> 10, rem = i & 1023;
            int n = rem >> 3, q = rem & 7;
            uint4 v = *(const uint4*)(&g_Wt[s][w][(size_t)(nbase + n) * Dd + c * 64 + q * 8]);
            *(uint4*)(smem + K3_B_OFF + s * 16384 + SW128(n * 128 + q * 16)) = v;
        }
        __syncthreads();

        #pragma unroll
        for (int ks = 0; ks < 4; ks++) {
            const uint32_t kx = (uint32_t)(ks * 32);
            uint32_t af[2][2][4];    // [split][mblk][frag]
            #pragma unroll
            for (int s = 0; s < 2; s++)
                #pragma unroll
                for (int mb = 0; mb < 2; mb++)
                    ldsm_x4(af[s][mb], a_base[mb] + s * 16384 + (kx ^ a_kmask[mb]));
            #pragma unroll
            for (int p = 0; p < 4; p++) {
                uint32_t b0[4];
                ldsm_x4(b0, b_base[p] + (kx ^ b_kmask[p]));          // split 0
                // pass (0,0) and (1,0)
                #pragma unroll
                for (int sa = 0; sa < 2; sa++) {
                    mma_fp16(acc[0][2 * p],     af[sa][0], b0 + 0);
                    mma_fp16(acc[0][2 * p + 1], af[sa][0], b0 + 2);
                    mma_fp16(acc[1][2 * p],     af[sa][1], b0 + 0);
                    mma_fp16(acc[1][2 * p + 1], af[sa][1], b0 + 2);
                }
                uint32_t b1[4];
                ldsm_x4(b1, b_base[p] + 16384 + (kx ^ b_kmask[p]));  // split 1
                // pass (0,1)
                mma_fp16(acc[0][2 * p],     af[0][0], b1 + 0);
                mma_fp16(acc[0][2 * p + 1], af[0][0], b1 + 2);
                mma_fp16(acc[1][2 * p],     af[0][1], b1 + 0);
                mma_fp16(acc[1][2 * p + 1], af[0][1], b1 + 2);
            }
        }
        __syncthreads();
    }

    // ---- epilogue: unscale by 1/16 (exact), fp32 stores --------------------
    const int r0 = rowbase + wm * 32 + (lane >> 2);
    const int c0 = nbase + wn * 64 + (lane & 3) * 2;
    #pragma unroll
    for (int mb = 0; mb < 2; mb++)
        #pragma unroll
        for (int nb = 0; nb < 8; nb++) {
            float2 lo = make_float2(acc[mb][nb][0] * WUNSCALE, acc[mb][nb][1] * WUNSCALE);
            float2 hi = make_float2(acc[mb][nb][2] * WUNSCALE, acc[mb][nb][3] * WUNSCALE);
            *(float2*)(out + (size_t)(r0 + mb * 16)     * Dd + c0 + nb * 8) = lo;
            *(float2*)(out + (size_t)(r0 + mb * 16 + 8) * Dd + c0 + nb * 8) = hi;
        }
}

// ---------------- k4: persistent decode, NB=2 batches per block -------------
struct K4Smem {
    float q[NB][Dd];
    float heads[NB][Dd];
    float cc[NB][Nn][9];
    float pp[NB][Hh][Nn + 4];
    float ls[NB][Nn];
    int   list[NB][Nn];
    float er[NB][Dd];
    float sum[NB][Hh];
    int   sel[NB];
    int   cnt;
};

__device__ __forceinline__ void k4_finalize_q(K4Smem& S, int tid, int mlp,
                                              const float* __restrict__ W1,
                                              const float* __restrict__ b1,
                                              const float* __restrict__ W2,
                                              const float* __restrict__ b2)
{
    if (mlp) {
        __syncthreads();
        float m1[NB];
        #pragma unroll
        for (int bb = 0; bb < NB; bb++) m1[bb] = b1[tid];
        #pragma unroll 8
        for (int k = 0; k < Dd; k++) {
            float wv = W1[k * Dd + tid];
            #pragma unroll
            for (int bb = 0; bb < NB; bb++) m1[bb] += S.q[bb][k] * wv;
        }
        #pragma unroll
        for (int bb = 0; bb < NB; bb++) S.er[bb][tid] = fmaxf(m1[bb], 0.0f);
        __syncthreads();
        float m2[NB];
        #pragma unroll
        for (int bb = 0; bb < NB; bb++) m2[bb] = b2[tid];
        #pragma unroll 8
        for (int k = 0; k < Dd; k++) {
            float wv = W2[k * Dd + tid];
            #pragma unroll
            for (int bb = 0; bb < NB; bb++) m2[bb] += S.er[bb][k] * wv;
        }
        __syncthreads();
        #pragma unroll
        for (int bb = 0; bb < NB; bb++)
            S.q[bb][tid] = (S.q[bb][tid] + m2[bb]) * INV_SQRT_DH;
    } else {
        #pragma unroll
        for (int bb = 0; bb < NB; bb++) S.q[bb][tid] *= INV_SQRT_DH;
    }
    __syncthreads();
}

__global__ void __launch_bounds__(256, 4) k4_decode(const float* __restrict__ E,
                                                    const float* __restrict__ coords,
                                                    const float* __restrict__ Ws,
                                                    const float* __restrict__ W1,
                                                    const float* __restrict__ b1,
                                                    const float* __restrict__ W2,
                                                    const float* __restrict__ b2,
                                                    float* __restrict__ out)
{
    extern __shared__ char smem_raw[];
    K4Smem& S = *(K4Smem*)smem_raw;

    const int b0 = blockIdx.x * NB;
    const int tid = threadIdx.x;
    const int warp = tid >> 5, lane = tid & 31;
    const int wb  = warp >> 2;
    const int wj0 = warp & 3;
    const int mlp = g_mlp;

    if (tid < Nn) {
        #pragma unroll
        for (int bb = 0; bb < NB; bb++) S.list[bb][tid] = tid;
    }
    if (tid == 0) S.cnt = Nn;
    #pragma unroll
    for (int bb = 0; bb < NB; bb++)
        S.q[bb][tid] = g_q0[(b0 + bb) * Dd + tid];
    k4_finalize_q(S, tid, mlp, W1, b1, W2, b2);

    const float* Kbase  = g_K   + (size_t)b0 * Nn * Dd;
    const float* Vbase  = g_V   + (size_t)b0 * Nn * Dd;
    const float* LKbase = g_LK2 + (size_t)b0 * Nn * Dd;

    float ll = 0.f, cost = 0.f;
    float fx = 0.f, fy = 0.f, px = 0.f, py = 0.f;
    float fctx[NB] = {0.f, 0.f};

    for (int t = 0; t < Nn; t++) {
        const int cnt = S.cnt;

        {
            const float4* q4 = (const float4*)S.q[wb];
            float4 qa = q4[lane], qb = q4[lane + 32];
            const float* Kb = Kbase + (size_t)wb * Nn * Dd;
            const int* lst = S.list[wb];
            for (int j = wj0; j < cnt; j += 4) {
                const float4* Kr = (const float4*)(Kb + (size_t)lst[j] * Dd);
                float4 k0 = __ldcg(Kr + lane);
                float4 k1 = __ldcg(Kr + lane + 32);
                float alo = k0.x * qa.x + k0.y * qa.y + k0.z * qa.z + k0.w * qa.w;
                float ahi = k1.x * qb.x + k1.y * qb.y + k1.z * qb.z + k1.w * qb.w;
                #pragma unroll
                for (int o = 1; o < 8; o <<= 1) {
                    alo += __shfl_xor_sync(0xffffffffu, alo, o);
                    ahi += __shfl_xor_sync(0xffffffffu, ahi, o);
                }
                if ((lane & 7) == 0) {
                    int hg = lane >> 3;
                    S.cc[wb][j][hg]     = alo;
                    S.cc[wb][j][4 + hg] = ahi;
                }
            }
        }
        __syncthreads();

        {
            const int h = warp;
            #pragma unroll
            for (int bb = 0; bb < NB; bb++) {
                float m = NEGV;
                for (int j = lane; j < cnt; j += 32) m = fmaxf(m, S.cc[bb][j][h]);
                #pragma unroll
                for (int o = 16; o; o >>= 1)
                    m = fmaxf(m, __shfl_xor_sync(0xffffffffu, m, o));
                float s = 0.f;
                for (int j = lane; j < cnt; j += 32) {
                    float e = expf(S.cc[bb][j][h] - m);
                    S.pp[bb][h][j] = e;
                    s += e;
                }
                #pragma unroll
                for (int o = 16; o; o >>= 1) s += __shfl_xor_sync(0xffffffffu, s, o);
                if (lane == 0) S.sum[bb][h] = s;
            }
        }
        __syncthreads();

        {
            const int d = tid, h = tid >> 5;
            float a[NB] = {0.f, 0.f};
            const float* Vd = Vbase + d;
            #pragma unroll 2
            for (int j = 0; j < cnt; j++) {
                #pragma unroll
                for (int bb = 0; bb < NB; bb++)
                    a[bb] += S.pp[bb][h][j] *
                             __ldcg(Vd + ((size_t)bb * Nn + S.list[bb][j]) * Dd);
            }
            #pragma unroll
            for (int bb = 0; bb < NB; bb++)
                S.heads[bb][d] = a[bb] / S.sum[bb][h];
        }
        __syncthreads();

        {
            const float4* h4 = (const float4*)S.heads[wb];
            float4 ha = h4[lane], hb = h4[lane + 32];
            const float* Lb = LKbase + (size_t)wb * Nn * Dd;
            const int* lst = S.list[wb];
            for (int j = wj0; j < cnt; j += 4) {
                const float4* Lr = (const float4*)(Lb + (size_t)lst[j] * Dd);
                float4 l0 = __ldcg(Lr + lane);
                float4 l1 = __ldcg(Lr + lane + 32);
                float a = l0.x * ha.x + l0.y * ha.y + l0.z * ha.z + l0.w * ha.w
                        + l1.x * hb.x + l1.y * hb.y + l1.z * hb.z + l1.w * hb.w;
                #pragma unroll
                for (int o = 16; o; o >>= 1) a += __shfl_xor_sync(0xffffffffu, a, o);
                if (lane == 0) S.ls[wb][j] = CLIPV * tanhf(a * INV_SQRT_D);
            }
        }
        __syncthreads();

        if (warp < NB) {
            const int bb = warp;
            float m = NEGV; int mj = 0;
            for (int j = lane; j < cnt; j += 32) {
                float v = S.ls[bb][j];
                if (v > m) { m = v; mj = j; }
            }
            #pragma unroll
            for (int o = 16; o; o >>= 1) {
                float vm = __shfl_xor_sync(0xffffffffu, m, o);
                int   vj = __shfl_xor_sync(0xffffffffu, mj, o);
                if (vm > m || (vm == m && vj < mj)) { m = vm; mj = vj; }
            }
            float s = 0.f;
            for (int j = lane; j < cnt; j += 32) s += expf(S.ls[bb][j] - m);
            #pragma unroll
            for (int o = 16; o; o >>= 1) s += __shfl_xor_sync(0xffffffffu, s, o);
            if (lane == 0) {
                int node = S.list[bb][mj];
                S.sel[bb] = node;
                ll += S.ls[bb][mj] - (m + logf(s));
                float cx = coords[((size_t)(b0 + bb) * Nn + node) * 2 + 0];
                float cy = coords[((size_t)(b0 + bb) * Nn + node) * 2 + 1];
                if (t == 0) { fx = cx; fy = cy; }
                else {
                    float dx = cx - px, dy = cy - py;
                    cost += sqrtf(dx * dx + dy * dy);
                }
                px = cx; py = cy;
                S.list[bb][mj] = S.list[bb][cnt - 1];
            }
        }
        if (tid == 0) S.cnt = cnt - 1;
        __syncthreads();

        if (t == 0) {
            #pragma unroll
            for (int bb = 0; bb < NB; bb++)
                S.er[bb][tid] =
                    E[((size_t)(b0 + bb) * Nn + S.sel[bb]) * Dd + tid];
            __syncthreads();
            float f[NB] = {0.f, 0.f};
            #pragma unroll 8
            for (int k = 0; k < Dd; k++) {
                float wv = Ws[k * Dd + tid];
                #pragma unroll
                for (int bb = 0; bb < NB; bb++) f[bb] += S.er[bb][k] * wv;
            }
            #pragma unroll
            for (int bb = 0; bb < NB; bb++) fctx[bb] = f[bb];
            __syncthreads();
        }

        if (t < Nn - 1) {
            float base[NB];
            #pragma unroll
            for (int bb = 0; bb < NB; bb++)
                base[bb] = fctx[bb] +
                    __ldcg(&g_P[((size_t)(b0 + bb) * Nn + S.sel[bb]) * Dd + tid]);
            float a0 = 0.f, a1 = 0.f, b0a = 0.f, b1a = 0.f;
            const float* Wp = g_Woc + tid;
            #pragma unroll 8
            for (int k = 0; k < Dd; k += 2) {
                float wv0 = Wp[(size_t)k * Dd];
                float wv1 = Wp[(size_t)(k + 1) * Dd];
                a0  += S.heads[0][k]     * wv0;
                b0a += S.heads[1][k]     * wv0;
                a1  += S.heads[0][k + 1] * wv1;
                b1a += S.heads[1][k + 1] * wv1;
            }
            __syncthreads();
            S.q[0][tid] = base[0] + (a0 + a1);
            S.q[1][tid] = base[1] + (b0a + b1a);
            k4_finalize_q(S, tid, mlp, W1, b1, W2, b2);
        }
    }

    if (warp < NB && lane == 0) {
        float dx = px - fx, dy = py - fy;
        cost += sqrtf(dx * dx + dy * dy);
        out[b0 + warp]      = cost;
        out[Bq + b0 + warp] = ll;
    }
}

// ---------------- launcher ---------------------------------------------------
extern "C" void kernel_launch(void* const* d_in, const int* in_sizes, int n_in,
                              void* d_out, int out_size)
{
    const float* coords = (const float*)d_in[0];
    const float* E      = (const float*)d_in[1];
    const float* Wk     = (const float*)d_in[2];
    const float* Wv     = (const float*)d_in[3];
    const float* Wlk    = (const float*)d_in[4];
    const float* Wo     = (const float*)d_in[5];
    const float* Wc     = (const float*)d_in[6];
    const float* Ws     = (const float*)d_in[7];
    const float* Wph    = (const float*)d_in[8];
    const float* W1     = (const float*)d_in[9];
    const float* b1     = (const float*)d_in[10];
    const float* W2     = (const float*)d_in[11];
    const float* b2     = (const float*)d_in[12];
    float* out = (float*)d_out;

    const int k4_smem = (int)sizeof(K4Smem);
    cudaFuncSetAttribute(k4_decode, cudaFuncAttributeMaxDynamicSharedMemorySize,
                         k4_smem);
    cudaFuncSetAttribute(k3t_mma, cudaFuncAttributeMaxDynamicSharedMemorySize,
                         K3T_SMEM);

    k0_prep<<<2, 256>>>(Wo, W2, b2);
    k1_weights<<<513, 256>>>(Wo, Wc, Wlk, Ws, Wph);
    k_splitE<<<8192, 256>>>(E);
    {
        dim3 gw(4, 256);
        k_splitW<<<gw, 256>>>(Wk, Wv, Ws);
    }
    k2_q0<<<Bq, 256>>>(E, Wc);
    {
        dim3 g3(ROWS_TOTAL / 128, 2, 4);
        k3t_mma<<<g3, 256, K3T_SMEM>>>();
    }
    k4_decode<<<Bq / NB, 256, k4_smem>>>(E, coords, Ws, W1, b1, W2, b2, out);
}